// round 1
// baseline (speedup 1.0000x reference)
#include <cuda_runtime.h>
#include <stdint.h>

#define B_ROWS 8192
#define D_DIM  512
#define N_OFF  16

struct OffArgs { int off[N_OFF]; };

// ---------------------------------------------------------------------------
// Device kernel: warp-per-row. Query row held in registers, 16 item rows
// streamed from L2, butterfly reduce, softmax on lane 0.
// ---------------------------------------------------------------------------
__global__ __launch_bounds__(256) void ibns_kernel(
    const float* __restrict__ q,
    const float* __restrict__ items,
    float* __restrict__ out,
    OffArgs oa)
{
    const int gw   = (blockIdx.x * 256 + threadIdx.x) >> 5;   // global warp = row b
    const int lane = threadIdx.x & 31;
    if (gw >= B_ROWS) return;

    const float4* qr = reinterpret_cast<const float4*>(q + (size_t)gw * D_DIM);
    const float4 q0 = qr[lane];
    const float4 q1 = qr[lane + 32];
    const float4 q2 = qr[lane + 64];
    const float4 q3 = qr[lane + 96];

    float s[N_OFF];

#pragma unroll 4
    for (int n = 0; n < N_OFF; n++) {
        const int j = (gw + oa.off[n]) & (B_ROWS - 1);
        const float4* ir = reinterpret_cast<const float4*>(items + (size_t)j * D_DIM);
        const float4 a = ir[lane];
        const float4 b = ir[lane + 32];
        const float4 c = ir[lane + 64];
        const float4 d = ir[lane + 96];
        float acc = 0.f;
        acc = fmaf(q0.x, a.x, acc); acc = fmaf(q0.y, a.y, acc);
        acc = fmaf(q0.z, a.z, acc); acc = fmaf(q0.w, a.w, acc);
        acc = fmaf(q1.x, b.x, acc); acc = fmaf(q1.y, b.y, acc);
        acc = fmaf(q1.z, b.z, acc); acc = fmaf(q1.w, b.w, acc);
        acc = fmaf(q2.x, c.x, acc); acc = fmaf(q2.y, c.y, acc);
        acc = fmaf(q2.z, c.z, acc); acc = fmaf(q2.w, c.w, acc);
        acc = fmaf(q3.x, d.x, acc); acc = fmaf(q3.y, d.y, acc);
        acc = fmaf(q3.z, d.z, acc); acc = fmaf(q3.w, d.w, acc);
        s[n] = acc;
    }

    // Warp butterfly reductions: after this every lane holds all 16 full dots.
#pragma unroll
    for (int n = 0; n < N_OFF; n++) {
        float v = s[n];
        v += __shfl_xor_sync(0xffffffffu, v, 16);
        v += __shfl_xor_sync(0xffffffffu, v, 8);
        v += __shfl_xor_sync(0xffffffffu, v, 4);
        v += __shfl_xor_sync(0xffffffffu, v, 2);
        v += __shfl_xor_sync(0xffffffffu, v, 1);
        s[n] = v;
    }

    if (lane == 0) {
        float mx = s[0];
#pragma unroll
        for (int n = 1; n < N_OFF; n++) mx = fmaxf(mx, s[n]);
        float denom = 0.f;
#pragma unroll
        for (int n = 0; n < N_OFF; n++) denom += __expf((s[n] - mx) * 10.0f);
        out[gw] = __expf((s[0] - mx) * 10.0f) / denom;
    }
}

// ---------------------------------------------------------------------------
// Host-side exact replication of numpy's
//   np.random.default_rng(0).choice(np.arange(1, 8192), size=15, replace=False)
// SeedSequence(0) -> PCG64 (XSL-RR 128/64) -> Generator.choice Floyd's algorithm
// with hash set + final _shuffle_int. Deterministic, stateless, no allocation.
// ---------------------------------------------------------------------------
namespace ibns_rng {

typedef unsigned __int128 u128;

struct Pcg {
    u128 state, inc;
    int has32;
    uint32_t buf;
};

static inline uint64_t rotr64(uint64_t x, uint32_t r) {
    return (x >> r) | (x << ((64u - r) & 63u));
}

static const u128 PCG_MULT = (((u128)2549297995355413924ULL) << 64) | 4865540595714422341ULL;

static inline uint64_t pcg_next64(Pcg* p) {
    p->state = p->state * PCG_MULT + p->inc;
    uint64_t hi = (uint64_t)(p->state >> 64);
    uint64_t lo = (uint64_t)p->state;
    uint32_t rot = (uint32_t)(p->state >> 122);
    return rotr64(hi ^ lo, rot);
}

static inline uint32_t pcg_next32(Pcg* p) {
    if (p->has32) { p->has32 = 0; return p->buf; }
    uint64_t v = pcg_next64(p);
    p->has32 = 1;
    p->buf = (uint32_t)(v >> 32);
    return (uint32_t)v;
}

// numpy distributions.c bounded_lemire_uint32: inclusive range [0, rng]
static inline uint32_t lemire32(Pcg* p, uint32_t rng) {
    if (rng == 0) return 0;
    const uint32_t rng_excl = rng + 1u;
    uint64_t m = (uint64_t)pcg_next32(p) * (uint64_t)rng_excl;
    uint32_t leftover = (uint32_t)m;
    if (leftover < rng_excl) {
        const uint32_t threshold = (0xFFFFFFFFu - rng) % rng_excl;
        while (leftover < threshold) {
            m = (uint64_t)pcg_next32(p) * (uint64_t)rng_excl;
            leftover = (uint32_t)m;
        }
    }
    return (uint32_t)(m >> 32);
}

// --- SeedSequence constants (numpy bit_generator.pyx, imneme seed_seq_fe) ---
static const uint32_t INIT_A = 0x43b0d7e5u, MULT_A = 0x931e8875u;
static const uint32_t INIT_B = 0x8b51f9ddu, MULT_B = 0x58f38dedu;
static const uint32_t MIX_L  = 0xca01f9ddu, MIX_R  = 0x4973f715u;

static inline uint32_t hashmix(uint32_t v, uint32_t* hc) {
    v ^= *hc;
    *hc = (uint32_t)(*hc * MULT_A);
    v = (uint32_t)(v * *hc);
    v ^= v >> 16;
    return v;
}
static inline uint32_t mixfn(uint32_t x, uint32_t y) {
    uint32_t r = (uint32_t)(MIX_L * x - MIX_R * y);
    r ^= r >> 16;
    return r;
}

static void compute_offsets(int* off16) {
    // SeedSequence(0): entropy = [0], pool_size = 4
    uint32_t pool[4];
    uint32_t hc = INIT_A;
    // fill pool: entropy word 0, then zeros
    pool[0] = hashmix(0u, &hc);
    pool[1] = hashmix(0u, &hc);
    pool[2] = hashmix(0u, &hc);
    pool[3] = hashmix(0u, &hc);
    // all-pairs mix
    for (int i_src = 0; i_src < 4; i_src++)
        for (int i_dst = 0; i_dst < 4; i_dst++)
            if (i_src != i_dst)
                pool[i_dst] = mixfn(pool[i_dst], hashmix(pool[i_src], &hc));

    // generate_state(4, uint64) == 8 uint32 words, little-endian pairing
    uint32_t w[8];
    hc = INIT_B;
    for (int i = 0; i < 8; i++) {
        uint32_t dv = pool[i & 3];
        dv ^= hc;
        hc = (uint32_t)(hc * MULT_B);
        dv = (uint32_t)(dv * hc);
        dv ^= dv >> 16;
        w[i] = dv;
    }
    uint64_t val[4];
    for (int k = 0; k < 4; k++)
        val[k] = (uint64_t)w[2 * k] | ((uint64_t)w[2 * k + 1] << 32);

    // PCG64 seeding: initstate = (val0<<64)|val1, initseq = (val2<<64)|val3
    u128 initstate = (((u128)val[0]) << 64) | val[1];
    u128 initseq   = (((u128)val[2]) << 64) | val[3];
    Pcg p;
    p.has32 = 0; p.buf = 0;
    p.state = 0;
    p.inc = (initseq << 1) | 1;
    p.state = p.state * PCG_MULT + p.inc;   // step
    p.state += initstate;
    p.state = p.state * PCG_MULT + p.inc;   // step

    // Generator.choice(pop_size=8191, size=15, replace=False, p=None):
    // Floyd's algorithm with hash set (set_size=32, mask=31), then shuffle.
    const int pop_size = 8191, size = 15;
    const uint64_t NONE = ~(uint64_t)0;
    uint64_t hset[32];
    for (int i = 0; i < 32; i++) hset[i] = NONE;
    int64_t idx[15];
    for (int j = pop_size - size; j < pop_size; j++) {
        uint64_t v = (uint64_t)lemire32(&p, (uint32_t)j);   // [0, j]
        uint32_t loc = (uint32_t)(v & 31u);
        while (hset[loc] != NONE && hset[loc] != v) loc = (loc + 1u) & 31u;
        if (hset[loc] == NONE) {
            hset[loc] = v;
            idx[j - (pop_size - size)] = (int64_t)v;
        } else {
            loc = (uint32_t)((uint32_t)j & 31u);
            while (hset[loc] != NONE) loc = (loc + 1u) & 31u;
            hset[loc] = (uint64_t)j;
            idx[j - (pop_size - size)] = (int64_t)j;
        }
    }
    // _shuffle_int(size=15, first=1)
    for (int i = size - 1; i >= 1; i--) {
        uint32_t j = lemire32(&p, (uint32_t)i);
        int64_t t = idx[j]; idx[j] = idx[i]; idx[i] = t;
    }

    // a = arange(1, 8192) -> offset value = idx + 1; prepend 0
    off16[0] = 0;
    for (int n = 0; n < 15; n++) off16[n + 1] = (int)(idx[n] + 1);
}

} // namespace ibns_rng

extern "C" void kernel_launch(void* const* d_in, const int* in_sizes, int n_in,
                              void* d_out, int out_size) {
    (void)in_sizes; (void)n_in; (void)out_size;
    OffArgs oa;
    ibns_rng::compute_offsets(oa.off);

    const float* q     = (const float*)d_in[0];
    const float* items = (const float*)d_in[1];
    float* out         = (float*)d_out;

    // 8192 warps, 8 warps per 256-thread CTA
    ibns_kernel<<<B_ROWS / 8, 256>>>(q, items, out, oa);
}